// round 10
// baseline (speedup 1.0000x reference)
#include <cuda_runtime.h>
#include <cuda_bf16.h>
#include <cstdint>
#include <math.h>

// ============================================================================
// QAConv int8 path: s[g,p,i,j] = <ker[p,i,:], gal[g,:,j]> on channel-L2-
// normalized features, per-column symmetric int8 quantization, IMMA
// m16n8k32 s8s8s32, exact s32 accumulation, factorized dequant in the fused
// dual-max epilogue, then BN/fc/LBN/sigmoid.
// ============================================================================

#define G_ 64
#define P_ 64
#define D_ 512
#define HW_ 192

__device__ int8_t g_kerA[(size_t)P_ * HW_ * D_];   // [p][i][k]  K-major s8
__device__ int8_t g_galB[(size_t)G_ * HW_ * D_];   // [g][j][k]  K-major s8
__device__ float  g_qf[128 * HW_];                 // quant factor 127/max|x|
__device__ float  g_dq[128 * HW_];                 // dequant max/(127*norm)
// index z: z<64 -> gal (B), z>=64 -> prob (A)

// ------------------------- Kernel 1: norms + max --------------------------
__global__ void __launch_bounds__(768) norm_kernel(const float* __restrict__ gal,
                                                   const float* __restrict__ prob) {
    __shared__ float ssum[4][HW_];
    __shared__ float smax[4][HW_];
    int b = blockIdx.x;                 // 0..127
    int j = threadIdx.x;                // 0..191
    int ty = threadIdx.y;               // 0..3
    const float* src = (b < 64) ? (gal + (size_t)b * D_ * HW_)
                                : (prob + (size_t)(b - 64) * D_ * HW_);
    float ss = 0.f, mm = 0.f;
#pragma unroll 8
    for (int dd = 0; dd < 128; dd++) {
        float v = src[(size_t)(ty * 128 + dd) * HW_ + j];
        ss += v * v;
        mm = fmaxf(mm, fabsf(v));
    }
    ssum[ty][j] = ss;
    smax[ty][j] = mm;
    __syncthreads();
    if (ty == 0) {
        ss = ssum[0][j] + ssum[1][j] + ssum[2][j] + ssum[3][j];
        mm = fmaxf(fmaxf(smax[0][j], smax[1][j]), fmaxf(smax[2][j], smax[3][j]));
        float n = fmaxf(sqrtf(ss), 1e-12f);
        mm = fmaxf(mm, 1e-20f);
        g_qf[b * HW_ + j] = 127.f / mm;
        g_dq[b * HW_ + j] = mm / (127.f * n);
    }
}

// ------------------- Kernel 2: transpose + quantize to s8 -----------------
__global__ void prep_kernel(const float* __restrict__ gal,
                            const float* __restrict__ prob) {
    __shared__ float tile[32][33];
    __shared__ float fj[32];
    int z = blockIdx.z;                 // 0..127
    int d0 = blockIdx.x * 32;           // 16 tiles
    int j0 = blockIdx.y * 32;           // 6 tiles
    int tx = threadIdx.x, ty = threadIdx.y;  // 32 x 8
    const float* src;
    int8_t* dst;
    if (z < 64) {
        src = gal + (size_t)z * D_ * HW_;
        dst = g_galB + (size_t)z * HW_ * D_;
    } else {
        src = prob + (size_t)(z - 64) * D_ * HW_;
        dst = g_kerA + (size_t)(z - 64) * HW_ * D_;
    }
#pragma unroll
    for (int r = 0; r < 32; r += 8)
        tile[ty + r][tx] = src[(size_t)(d0 + ty + r) * HW_ + j0 + tx];
    if (ty == 0) fj[tx] = g_qf[z * HW_ + j0 + tx];
    __syncthreads();

    int tid = ty * 32 + tx;
    int jl = tid >> 3;                  // 0..31
    int d4 = (tid & 7) * 4;             // 0,4,..,28
    float f = fj[jl];
    char4 c;
    {
        float v0 = tile[d4 + 0][jl] * f, v1 = tile[d4 + 1][jl] * f;
        float v2 = tile[d4 + 2][jl] * f, v3 = tile[d4 + 3][jl] * f;
        c.x = (char)__float2int_rn(fminf(fmaxf(v0, -127.f), 127.f));
        c.y = (char)__float2int_rn(fminf(fmaxf(v1, -127.f), 127.f));
        c.z = (char)__float2int_rn(fminf(fmaxf(v2, -127.f), 127.f));
        c.w = (char)__float2int_rn(fminf(fmaxf(v3, -127.f), 127.f));
    }
    *(char4*)(dst + (size_t)(j0 + jl) * D_ + d0 + d4) = c;
}

// ------------------------------ helpers ------------------------------
__device__ __forceinline__ uint32_t smem_u32(const void* p) {
    return (uint32_t)__cvta_generic_to_shared(p);
}
__device__ __forceinline__ void cpasync16(uint32_t dst, const void* src) {
    asm volatile("cp.async.cg.shared.global [%0], [%1], 16;"
                 :: "r"(dst), "l"(src) : "memory");
}
__device__ __forceinline__ void ldsm4(uint32_t& r0, uint32_t& r1,
                                      uint32_t& r2, uint32_t& r3,
                                      uint32_t addr) {
    asm volatile("ldmatrix.sync.aligned.m8n8.x4.shared.b16 {%0,%1,%2,%3}, [%4];"
                 : "=r"(r0), "=r"(r1), "=r"(r2), "=r"(r3) : "r"(addr));
}
__device__ __forceinline__ void mma16832(int* c, const uint32_t* a,
                                         uint32_t b0, uint32_t b1) {
    asm volatile(
        "mma.sync.aligned.m16n8k32.row.col.s32.s8.s8.s32 "
        "{%0,%1,%2,%3}, {%4,%5,%6,%7}, {%8,%9}, {%0,%1,%2,%3};"
        : "+r"(c[0]), "+r"(c[1]), "+r"(c[2]), "+r"(c[3])
        : "r"(a[0]), "r"(a[1]), "r"(a[2]), "r"(a[3]), "r"(b0), "r"(b1));
}

#define SWZ(x) ((x) ^ (((x) >> 3) & 0x70))

// SMEM: 3-stage ring; each stage = A 192x128B (24KB) + B 192x128B (24KB)
#define OFF_BUF    1024
#define CH_BYTES   49152
#define STG(s)     (OFF_BUF + (s) * CH_BYTES)
#define OFF_ROWP   (OFF_BUF + 3 * CH_BYTES)            // rowp[2][192] f32
#define OFF_COLP   (OFF_ROWP + 2 * 192 * 4)            // colp[4][192] f32
#define OFF_RED    (OFF_COLP + 4 * 192 * 4)            // red[8]
#define SMEM_BYTES (OFF_RED + 64)

// ----------------- Kernel 3: int8 GEMM + fused epilogue -------------------
__global__ void __launch_bounds__(256, 1) qaconv_gemm(
    const float* __restrict__ bnw, const float* __restrict__ bnb,
    const float* __restrict__ bnm, const float* __restrict__ bnv,
    const float* __restrict__ fcw, const float* __restrict__ fcb,
    const float* __restrict__ lbnw, const float* __restrict__ lbnb,
    const float* __restrict__ lbnm, const float* __restrict__ lbnv,
    float* __restrict__ out)
{
    extern __shared__ char smem[];
    const uint32_t sbase = smem_u32(smem);
    const int tid = threadIdx.x;
    const int wid = tid >> 5;
    const int lane = tid & 31;
    const int warp_m = wid & 3;        // 4 strips of 48 rows (probe i)
    const int warp_n = wid >> 2;       // 2 strips of 96 cols (gallery j)
    const int gidx = blockIdx.x >> 6;
    const int pidx = blockIdx.x & 63;

    const int8_t* Ag = g_kerA + (size_t)pidx * HW_ * D_;  // [192][512] s8
    const int8_t* Bg = g_galB + (size_t)gidx * HW_ * D_;  // [192][512] s8

    int acc[3][12][4];
#pragma unroll
    for (int mt = 0; mt < 3; mt++)
#pragma unroll
        for (int nt = 0; nt < 12; nt++)
#pragma unroll
            for (int q = 0; q < 4; q++) acc[mt][nt][q] = 0;

    // chunk = K=128 bytes/row. 4 chunks. 3072 16B granules, 12 per thread.
#define LOAD_CHUNK(c, st)                                                      \
    {                                                                          \
        const uint32_t sb_ = sbase + STG(st);                                  \
        _Pragma("unroll")                                                      \
        for (int i = 0; i < 12; i++) {                                         \
            int gid2 = tid + i * 256;                                          \
            bool isA = gid2 < 1536;                                            \
            int lg = isA ? gid2 : gid2 - 1536;                                 \
            int row = lg >> 3, seg = lg & 7;                                   \
            const int8_t* src =                                                \
                (isA ? Ag : Bg) + (size_t)row * D_ + (c) * 128 + seg * 16;     \
            uint32_t dst = sb_ + (isA ? 0 : 24576) + SWZ(row * 128 + seg * 16);\
            cpasync16(dst, src);                                               \
        }                                                                      \
        asm volatile("cp.async.commit_group;" ::: "memory");                   \
    }

    LOAD_CHUNK(0, 0);
    LOAD_CHUNK(1, 1);

#pragma unroll 1
    for (int c = 0; c < 4; c++) {
        if (c == 3) asm volatile("cp.async.wait_group 0;" ::: "memory");
        else        asm volatile("cp.async.wait_group 1;" ::: "memory");
        __syncthreads();

        const uint32_t ab = sbase + STG(c % 3);
        const uint32_t bb = ab + 24576;
        const int arowb = (warp_m * 48 + (lane & 15)) * 128;
        const int brow  = warp_n * 96 + (lane & 7) + ((lane >> 4) << 3);
#pragma unroll
        for (int ks = 0; ks < 4; ks++) {
            const int akb = ks * 32 + ((lane >> 4) << 4);
            const int bkb = ks * 32 + (((lane >> 3) & 1) << 4);
            uint32_t a[3][4];
#pragma unroll
            for (int mt = 0; mt < 3; mt++)
                ldsm4(a[mt][0], a[mt][1], a[mt][2], a[mt][3],
                      ab + SWZ(arowb + mt * 2048 + akb));
            uint32_t bf[6][4];
#pragma unroll
            for (int nt2 = 0; nt2 < 6; nt2++)
                ldsm4(bf[nt2][0], bf[nt2][1], bf[nt2][2], bf[nt2][3],
                      bb + SWZ((brow + nt2 * 16) * 128 + bkb));
#pragma unroll
            for (int mt = 0; mt < 3; mt++)
#pragma unroll
                for (int nt2 = 0; nt2 < 6; nt2++) {
                    mma16832(acc[mt][nt2 * 2 + 0], a[mt], bf[nt2][0], bf[nt2][1]);
                    mma16832(acc[mt][nt2 * 2 + 1], a[mt], bf[nt2][2], bf[nt2][3]);
                }
        }
        if (c < 2) LOAD_CHUNK(c + 2, (c + 2) % 3);
    }

    // -------- epilogue: dequant-factored dual max + BN/fc/LBN/sigmoid --------
    // acc[mt][nt][q]: row = warp_m*48 + mt*16 + lane/4 + (q>=2)*8
    //                 col = warp_n*96 + nt*8 + (lane%4)*2 + (q&1)
    float* rowp = (float*)(smem + OFF_ROWP);   // [2][192] max_j(acc*dqB), per i
    float* colp = (float*)(smem + OFF_COLP);   // [4][192] max_i(acc*dqA), per j

    const float* dqB = g_dq + gidx * HW_;
    const float* dqA = g_dq + (64 + pidx) * HW_;

    float dqB_r[24];
    {
        int cbase = warp_n * 96 + (lane & 3) * 2;
#pragma unroll
        for (int nt = 0; nt < 12; nt++) {
            dqB_r[2 * nt + 0] = dqB[cbase + nt * 8];
            dqB_r[2 * nt + 1] = dqB[cbase + nt * 8 + 1];
        }
    }
    float dqA_r[6];
    {
        int rbase = warp_m * 48 + (lane >> 2);
#pragma unroll
        for (int mt = 0; mt < 3; mt++) {
            dqA_r[2 * mt + 0] = dqA[rbase + mt * 16];
            dqA_r[2 * mt + 1] = dqA[rbase + mt * 16 + 8];
        }
    }

    // row maxes: fold dqB[j] per element (dqA factored out, applied later)
    float rm[6];
#pragma unroll
    for (int mt = 0; mt < 3; mt++) {
        float r0 = -3.4e38f, r1 = -3.4e38f;
#pragma unroll
        for (int nt = 0; nt < 12; nt++) {
            r0 = fmaxf(r0, fmaxf((float)acc[mt][nt][0] * dqB_r[2 * nt],
                                 (float)acc[mt][nt][1] * dqB_r[2 * nt + 1]));
            r1 = fmaxf(r1, fmaxf((float)acc[mt][nt][2] * dqB_r[2 * nt],
                                 (float)acc[mt][nt][3] * dqB_r[2 * nt + 1]));
        }
        rm[2 * mt] = r0; rm[2 * mt + 1] = r1;
    }
#pragma unroll
    for (int i = 0; i < 6; i++) {
        rm[i] = fmaxf(rm[i], __shfl_xor_sync(0xffffffffu, rm[i], 1));
        rm[i] = fmaxf(rm[i], __shfl_xor_sync(0xffffffffu, rm[i], 2));
    }
    if ((lane & 3) == 0) {
        int rbase = warp_m * 48 + (lane >> 2);
#pragma unroll
        for (int mt = 0; mt < 3; mt++) {
            rowp[warp_n * 192 + rbase + mt * 16]     = rm[2 * mt];
            rowp[warp_n * 192 + rbase + mt * 16 + 8] = rm[2 * mt + 1];
        }
    }

    // col maxes: fold dqA[i] per element (dqB applied later)
    float cm[24];
#pragma unroll
    for (int nt = 0; nt < 12; nt++) {
        float c0 = -3.4e38f, c1 = -3.4e38f;
#pragma unroll
        for (int mt = 0; mt < 3; mt++) {
            c0 = fmaxf(c0, fmaxf((float)acc[mt][nt][0] * dqA_r[2 * mt],
                                 (float)acc[mt][nt][2] * dqA_r[2 * mt + 1]));
            c1 = fmaxf(c1, fmaxf((float)acc[mt][nt][1] * dqA_r[2 * mt],
                                 (float)acc[mt][nt][3] * dqA_r[2 * mt + 1]));
        }
        cm[2 * nt] = c0; cm[2 * nt + 1] = c1;
    }
#pragma unroll
    for (int i = 0; i < 24; i++) {
        cm[i] = fmaxf(cm[i], __shfl_xor_sync(0xffffffffu, cm[i], 4));
        cm[i] = fmaxf(cm[i], __shfl_xor_sync(0xffffffffu, cm[i], 8));
        cm[i] = fmaxf(cm[i], __shfl_xor_sync(0xffffffffu, cm[i], 16));
    }
    if (lane < 4) {
        int cbase = warp_n * 96 + lane * 2;
#pragma unroll
        for (int nt = 0; nt < 12; nt++) {
            colp[warp_m * 192 + cbase + nt * 8]     = cm[2 * nt];
            colp[warp_m * 192 + cbase + nt * 8 + 1] = cm[2 * nt + 1];
        }
    }
    __syncthreads();

    float a_bn = bnw[0] * rsqrtf(bnv[0] + 1e-5f);
    float b_bn = bnb[0] - bnm[0] * a_bn;

    float part = 0.f;
    if (tid < 192) {
        float cmax = fmaxf(fmaxf(colp[tid], colp[192 + tid]),
                           fmaxf(colp[384 + tid], colp[576 + tid])) * dqB[tid];
        float rmax = fmaxf(rowp[tid], rowp[192 + tid]) * dqA[tid];
        part = fcw[tid]       * (a_bn * cmax + b_bn)     // s.max(axis=2), idx j
             + fcw[192 + tid] * (a_bn * rmax + b_bn);    // s.max(axis=3), idx i
    }
#pragma unroll
    for (int o = 16; o > 0; o >>= 1)
        part += __shfl_down_sync(0xffffffffu, part, o);
    float* red = (float*)(smem + OFF_RED);
    if (lane == 0) red[wid] = part;
    __syncthreads();
    if (tid == 0) {
        float s = red[0] + red[1] + red[2] + red[3] +
                  red[4] + red[5] + red[6] + red[7];
        s += fcb[0];
        float a2 = lbnw[0] * rsqrtf(lbnv[0] + 1e-5f);
        float y = (s - lbnm[0]) * a2 + lbnb[0];
        out[blockIdx.x] = 1.f / (1.f + expf(-y * 0.1f));
    }
}

// ------------------------------ launch ---------------------------------------
extern "C" void kernel_launch(void* const* d_in, const int* in_sizes, int n_in,
                              void* d_out, int out_size) {
    const float* gal  = (const float*)d_in[0];
    const float* prob = (const float*)d_in[1];
    const float* bnw  = (const float*)d_in[2];
    const float* bnb  = (const float*)d_in[3];
    const float* bnm  = (const float*)d_in[4];
    const float* bnv  = (const float*)d_in[5];
    const float* fcw  = (const float*)d_in[6];
    const float* fcb  = (const float*)d_in[7];
    const float* lbnw = (const float*)d_in[8];
    const float* lbnb = (const float*)d_in[9];
    const float* lbnm = (const float*)d_in[10];
    const float* lbnv = (const float*)d_in[11];
    float* out = (float*)d_out;

    cudaFuncSetAttribute(qaconv_gemm, cudaFuncAttributeMaxDynamicSharedMemorySize,
                         SMEM_BYTES);

    norm_kernel<<<128, dim3(192, 4)>>>(gal, prob);
    prep_kernel<<<dim3(16, 6, 128), dim3(32, 8)>>>(gal, prob);
    qaconv_gemm<<<G_ * P_, 256, SMEM_BYTES>>>(bnw, bnb, bnm, bnv, fcw, fcb,
                                              lbnw, lbnb, lbnm, lbnv, out);
}

// round 11
// speedup vs baseline: 2.1043x; 2.1043x over previous
#include <cuda_runtime.h>
#include <cuda_bf16.h>
#include <cstdint>
#include <math.h>

// ============================================================================
// QAConv fp8 path: s[g,p,i,j] = <ker[p,i,:], gal[g,:,j]> on channel-L2-
// normalized features. Per-column scaling to e4m3 (448/max|x|), legacy-path
// mma.sync.m16n8k32.f32.e4m3.e4m3.f32 (native FP8 on Blackwell tensor cores),
// factorized dequant in the fused dual-max epilogue, then BN/fc/LBN/sigmoid.
// ============================================================================

#define G_ 64
#define P_ 64
#define D_ 512
#define HW_ 192

__device__ uint8_t g_kerA[(size_t)P_ * HW_ * D_];  // [p][i][k]  K-major e4m3
__device__ uint8_t g_galB[(size_t)G_ * HW_ * D_];  // [g][j][k]  K-major e4m3
__device__ float   g_qf[128 * HW_];                // quant factor 448/max|x|
__device__ float   g_dq[128 * HW_];                // dequant max/(448*norm)
// index z: z<64 -> gal (B), z>=64 -> prob (A)

// ------------------------- Kernel 1: norms + max --------------------------
__global__ void __launch_bounds__(768) norm_kernel(const float* __restrict__ gal,
                                                   const float* __restrict__ prob) {
    __shared__ float ssum[4][HW_];
    __shared__ float smax[4][HW_];
    int b = blockIdx.x;                 // 0..127
    int j = threadIdx.x;                // 0..191
    int ty = threadIdx.y;               // 0..3
    const float* src = (b < 64) ? (gal + (size_t)b * D_ * HW_)
                                : (prob + (size_t)(b - 64) * D_ * HW_);
    float ss = 0.f, mm = 0.f;
#pragma unroll 8
    for (int dd = 0; dd < 128; dd++) {
        float v = src[(size_t)(ty * 128 + dd) * HW_ + j];
        ss += v * v;
        mm = fmaxf(mm, fabsf(v));
    }
    ssum[ty][j] = ss;
    smax[ty][j] = mm;
    __syncthreads();
    if (ty == 0) {
        ss = ssum[0][j] + ssum[1][j] + ssum[2][j] + ssum[3][j];
        mm = fmaxf(fmaxf(smax[0][j], smax[1][j]), fmaxf(smax[2][j], smax[3][j]));
        float n = fmaxf(sqrtf(ss), 1e-12f);
        mm = fmaxf(mm, 1e-20f);
        g_qf[b * HW_ + j] = 448.f / mm;
        g_dq[b * HW_ + j] = mm / (448.f * n);
    }
}

// ------------------- Kernel 2: transpose + quantize to e4m3 ----------------
__global__ void prep_kernel(const float* __restrict__ gal,
                            const float* __restrict__ prob) {
    __shared__ float tile[32][33];
    __shared__ float fj[32];
    int z = blockIdx.z;                 // 0..127
    int d0 = blockIdx.x * 32;           // 16 tiles
    int j0 = blockIdx.y * 32;           // 6 tiles
    int tx = threadIdx.x, ty = threadIdx.y;  // 32 x 8
    const float* src;
    uint8_t* dst;
    if (z < 64) {
        src = gal + (size_t)z * D_ * HW_;
        dst = g_galB + (size_t)z * HW_ * D_;
    } else {
        src = prob + (size_t)(z - 64) * D_ * HW_;
        dst = g_kerA + (size_t)(z - 64) * HW_ * D_;
    }
#pragma unroll
    for (int r = 0; r < 32; r += 8)
        tile[ty + r][tx] = src[(size_t)(d0 + ty + r) * HW_ + j0 + tx];
    if (ty == 0) fj[tx] = g_qf[z * HW_ + j0 + tx];
    __syncthreads();

    int tid = ty * 32 + tx;
    int jl = tid >> 3;                  // 0..31
    int d4 = (tid & 7) * 4;             // 0,4,..,28
    float f = fj[jl];
    float v0 = tile[d4 + 0][jl] * f, v1 = tile[d4 + 1][jl] * f;
    float v2 = tile[d4 + 2][jl] * f, v3 = tile[d4 + 3][jl] * f;
    uint16_t lo, hi;
    // d = {a_hi, b_lo}: pass (v1, v0) so byte0=v0, byte1=v1 (little-endian)
    asm("cvt.rn.satfinite.e4m3x2.f32 %0, %1, %2;" : "=h"(lo) : "f"(v1), "f"(v0));
    asm("cvt.rn.satfinite.e4m3x2.f32 %0, %1, %2;" : "=h"(hi) : "f"(v3), "f"(v2));
    uint32_t packed = (uint32_t)lo | ((uint32_t)hi << 16);
    *(uint32_t*)(dst + (size_t)(j0 + jl) * D_ + d0 + d4) = packed;
}

// ------------------------------ helpers ------------------------------
__device__ __forceinline__ uint32_t smem_u32(const void* p) {
    return (uint32_t)__cvta_generic_to_shared(p);
}
__device__ __forceinline__ void cpasync16(uint32_t dst, const void* src) {
    asm volatile("cp.async.cg.shared.global [%0], [%1], 16;"
                 :: "r"(dst), "l"(src) : "memory");
}
__device__ __forceinline__ void ldsm4(uint32_t& r0, uint32_t& r1,
                                      uint32_t& r2, uint32_t& r3,
                                      uint32_t addr) {
    asm volatile("ldmatrix.sync.aligned.m8n8.x4.shared.b16 {%0,%1,%2,%3}, [%4];"
                 : "=r"(r0), "=r"(r1), "=r"(r2), "=r"(r3) : "r"(addr));
}
__device__ __forceinline__ void mma_fp8(float* c, const uint32_t* a,
                                        uint32_t b0, uint32_t b1) {
    asm volatile(
        "mma.sync.aligned.m16n8k32.row.col.f32.e4m3.e4m3.f32 "
        "{%0,%1,%2,%3}, {%4,%5,%6,%7}, {%8,%9}, {%0,%1,%2,%3};"
        : "+f"(c[0]), "+f"(c[1]), "+f"(c[2]), "+f"(c[3])
        : "r"(a[0]), "r"(a[1]), "r"(a[2]), "r"(a[3]), "r"(b0), "r"(b1));
}

#define SWZ(x) ((x) ^ (((x) >> 3) & 0x70))

// SMEM: 3-stage ring; each stage = A 192x128B (24KB) + B 192x128B (24KB)
#define OFF_BUF    1024
#define CH_BYTES   49152
#define STG(s)     (OFF_BUF + (s) * CH_BYTES)
#define OFF_ROWP   (OFF_BUF + 3 * CH_BYTES)            // rowp[2][192] f32
#define OFF_COLP   (OFF_ROWP + 2 * 192 * 4)            // colp[4][192] f32
#define OFF_RED    (OFF_COLP + 4 * 192 * 4)            // red[8]
#define SMEM_BYTES (OFF_RED + 64)

// ----------------- Kernel 3: fp8 GEMM + fused epilogue -------------------
__global__ void __launch_bounds__(256, 1) qaconv_gemm(
    const float* __restrict__ bnw, const float* __restrict__ bnb,
    const float* __restrict__ bnm, const float* __restrict__ bnv,
    const float* __restrict__ fcw, const float* __restrict__ fcb,
    const float* __restrict__ lbnw, const float* __restrict__ lbnb,
    const float* __restrict__ lbnm, const float* __restrict__ lbnv,
    float* __restrict__ out)
{
    extern __shared__ char smem[];
    const uint32_t sbase = smem_u32(smem);
    const int tid = threadIdx.x;
    const int wid = tid >> 5;
    const int lane = tid & 31;
    const int warp_m = wid & 3;        // 4 strips of 48 rows (probe i)
    const int warp_n = wid >> 2;       // 2 strips of 96 cols (gallery j)
    const int gidx = blockIdx.x >> 6;
    const int pidx = blockIdx.x & 63;

    const uint8_t* Ag = g_kerA + (size_t)pidx * HW_ * D_;  // [192][512] e4m3
    const uint8_t* Bg = g_galB + (size_t)gidx * HW_ * D_;  // [192][512] e4m3

    float acc[3][12][4];
#pragma unroll
    for (int mt = 0; mt < 3; mt++)
#pragma unroll
        for (int nt = 0; nt < 12; nt++)
#pragma unroll
            for (int q = 0; q < 4; q++) acc[mt][nt][q] = 0.f;

    // chunk = K=128 bytes/row. 4 chunks. 3072 16B granules, 12 per thread.
#define LOAD_CHUNK(c, st)                                                      \
    {                                                                          \
        const uint32_t sb_ = sbase + STG(st);                                  \
        _Pragma("unroll")                                                      \
        for (int i = 0; i < 12; i++) {                                         \
            int gid2 = tid + i * 256;                                          \
            bool isA = gid2 < 1536;                                            \
            int lg = isA ? gid2 : gid2 - 1536;                                 \
            int row = lg >> 3, seg = lg & 7;                                   \
            const uint8_t* src =                                               \
                (isA ? Ag : Bg) + (size_t)row * D_ + (c) * 128 + seg * 16;     \
            uint32_t dst = sb_ + (isA ? 0 : 24576) + SWZ(row * 128 + seg * 16);\
            cpasync16(dst, src);                                               \
        }                                                                      \
        asm volatile("cp.async.commit_group;" ::: "memory");                   \
    }

    LOAD_CHUNK(0, 0);
    LOAD_CHUNK(1, 1);

#pragma unroll 1
    for (int c = 0; c < 4; c++) {
        if (c == 3) asm volatile("cp.async.wait_group 0;" ::: "memory");
        else        asm volatile("cp.async.wait_group 1;" ::: "memory");
        __syncthreads();

        const uint32_t ab = sbase + STG(c % 3);
        const uint32_t bb = ab + 24576;
        const int arowb = (warp_m * 48 + (lane & 15)) * 128;
        const int brow  = warp_n * 96 + (lane & 7) + ((lane >> 4) << 3);
#pragma unroll
        for (int ks = 0; ks < 4; ks++) {
            const int akb = ks * 32 + ((lane >> 4) << 4);
            const int bkb = ks * 32 + (((lane >> 3) & 1) << 4);
            uint32_t a[3][4];
#pragma unroll
            for (int mt = 0; mt < 3; mt++)
                ldsm4(a[mt][0], a[mt][1], a[mt][2], a[mt][3],
                      ab + SWZ(arowb + mt * 2048 + akb));
            uint32_t bf[6][4];
#pragma unroll
            for (int nt2 = 0; nt2 < 6; nt2++)
                ldsm4(bf[nt2][0], bf[nt2][1], bf[nt2][2], bf[nt2][3],
                      bb + SWZ((brow + nt2 * 16) * 128 + bkb));
#pragma unroll
            for (int mt = 0; mt < 3; mt++)
#pragma unroll
                for (int nt2 = 0; nt2 < 6; nt2++) {
                    mma_fp8(acc[mt][nt2 * 2 + 0], a[mt], bf[nt2][0], bf[nt2][1]);
                    mma_fp8(acc[mt][nt2 * 2 + 1], a[mt], bf[nt2][2], bf[nt2][3]);
                }
        }
        if (c < 2) LOAD_CHUNK(c + 2, (c + 2) % 3);
    }

    // -------- epilogue: dequant-factored dual max + BN/fc/LBN/sigmoid --------
    // acc[mt][nt][q]: row = warp_m*48 + mt*16 + lane/4 + (q>=2)*8
    //                 col = warp_n*96 + nt*8 + (lane%4)*2 + (q&1)
    float* rowp = (float*)(smem + OFF_ROWP);   // [2][192] max_j(acc*dqB), per i
    float* colp = (float*)(smem + OFF_COLP);   // [4][192] max_i(acc*dqA), per j

    const float* dqB = g_dq + gidx * HW_;
    const float* dqA = g_dq + (64 + pidx) * HW_;

    float dqB_r[24];
    {
        int cbase = warp_n * 96 + (lane & 3) * 2;
#pragma unroll
        for (int nt = 0; nt < 12; nt++) {
            dqB_r[2 * nt + 0] = dqB[cbase + nt * 8];
            dqB_r[2 * nt + 1] = dqB[cbase + nt * 8 + 1];
        }
    }
    float dqA_r[6];
    {
        int rbase = warp_m * 48 + (lane >> 2);
#pragma unroll
        for (int mt = 0; mt < 3; mt++) {
            dqA_r[2 * mt + 0] = dqA[rbase + mt * 16];
            dqA_r[2 * mt + 1] = dqA[rbase + mt * 16 + 8];
        }
    }

    // row maxes: fold dqB[j] per element (dqA factored out, applied later)
    float rm[6];
#pragma unroll
    for (int mt = 0; mt < 3; mt++) {
        float r0 = -3.4e38f, r1 = -3.4e38f;
#pragma unroll
        for (int nt = 0; nt < 12; nt++) {
            r0 = fmaxf(r0, fmaxf(acc[mt][nt][0] * dqB_r[2 * nt],
                                 acc[mt][nt][1] * dqB_r[2 * nt + 1]));
            r1 = fmaxf(r1, fmaxf(acc[mt][nt][2] * dqB_r[2 * nt],
                                 acc[mt][nt][3] * dqB_r[2 * nt + 1]));
        }
        rm[2 * mt] = r0; rm[2 * mt + 1] = r1;
    }
#pragma unroll
    for (int i = 0; i < 6; i++) {
        rm[i] = fmaxf(rm[i], __shfl_xor_sync(0xffffffffu, rm[i], 1));
        rm[i] = fmaxf(rm[i], __shfl_xor_sync(0xffffffffu, rm[i], 2));
    }
    if ((lane & 3) == 0) {
        int rbase = warp_m * 48 + (lane >> 2);
#pragma unroll
        for (int mt = 0; mt < 3; mt++) {
            rowp[warp_n * 192 + rbase + mt * 16]     = rm[2 * mt];
            rowp[warp_n * 192 + rbase + mt * 16 + 8] = rm[2 * mt + 1];
        }
    }

    // col maxes: fold dqA[i] per element (dqB applied later)
    float cm[24];
#pragma unroll
    for (int nt = 0; nt < 12; nt++) {
        float c0 = -3.4e38f, c1 = -3.4e38f;
#pragma unroll
        for (int mt = 0; mt < 3; mt++) {
            c0 = fmaxf(c0, fmaxf(acc[mt][nt][0] * dqA_r[2 * mt],
                                 acc[mt][nt][2] * dqA_r[2 * mt + 1]));
            c1 = fmaxf(c1, fmaxf(acc[mt][nt][1] * dqA_r[2 * mt],
                                 acc[mt][nt][3] * dqA_r[2 * mt + 1]));
        }
        cm[2 * nt] = c0; cm[2 * nt + 1] = c1;
    }
#pragma unroll
    for (int i = 0; i < 24; i++) {
        cm[i] = fmaxf(cm[i], __shfl_xor_sync(0xffffffffu, cm[i], 4));
        cm[i] = fmaxf(cm[i], __shfl_xor_sync(0xffffffffu, cm[i], 8));
        cm[i] = fmaxf(cm[i], __shfl_xor_sync(0xffffffffu, cm[i], 16));
    }
    if (lane < 4) {
        int cbase = warp_n * 96 + lane * 2;
#pragma unroll
        for (int nt = 0; nt < 12; nt++) {
            colp[warp_m * 192 + cbase + nt * 8]     = cm[2 * nt];
            colp[warp_m * 192 + cbase + nt * 8 + 1] = cm[2 * nt + 1];
        }
    }
    __syncthreads();

    float a_bn = bnw[0] * rsqrtf(bnv[0] + 1e-5f);
    float b_bn = bnb[0] - bnm[0] * a_bn;

    float part = 0.f;
    if (tid < 192) {
        float cmax = fmaxf(fmaxf(colp[tid], colp[192 + tid]),
                           fmaxf(colp[384 + tid], colp[576 + tid])) * dqB[tid];
        float rmax = fmaxf(rowp[tid], rowp[192 + tid]) * dqA[tid];
        part = fcw[tid]       * (a_bn * cmax + b_bn)     // s.max(axis=2), idx j
             + fcw[192 + tid] * (a_bn * rmax + b_bn);    // s.max(axis=3), idx i
    }
#pragma unroll
    for (int o = 16; o > 0; o >>= 1)
        part += __shfl_down_sync(0xffffffffu, part, o);
    float* red = (float*)(smem + OFF_RED);
    if (lane == 0) red[wid] = part;
    __syncthreads();
    if (tid == 0) {
        float s = red[0] + red[1] + red[2] + red[3] +
                  red[4] + red[5] + red[6] + red[7];
        s += fcb[0];
        float a2 = lbnw[0] * rsqrtf(lbnv[0] + 1e-5f);
        float y = (s - lbnm[0]) * a2 + lbnb[0];
        out[blockIdx.x] = 1.f / (1.f + expf(-y * 0.1f));
    }
}

// ------------------------------ launch ---------------------------------------
extern "C" void kernel_launch(void* const* d_in, const int* in_sizes, int n_in,
                              void* d_out, int out_size) {
    const float* gal  = (const float*)d_in[0];
    const float* prob = (const float*)d_in[1];
    const float* bnw  = (const float*)d_in[2];
    const float* bnb  = (const float*)d_in[3];
    const float* bnm  = (const float*)d_in[4];
    const float* bnv  = (const float*)d_in[5];
    const float* fcw  = (const float*)d_in[6];
    const float* fcb  = (const float*)d_in[7];
    const float* lbnw = (const float*)d_in[8];
    const float* lbnb = (const float*)d_in[9];
    const float* lbnm = (const float*)d_in[10];
    const float* lbnv = (const float*)d_in[11];
    float* out = (float*)d_out;

    cudaFuncSetAttribute(qaconv_gemm, cudaFuncAttributeMaxDynamicSharedMemorySize,
                         SMEM_BYTES);

    norm_kernel<<<128, dim3(192, 4)>>>(gal, prob);
    prep_kernel<<<dim3(16, 6, 128), dim3(32, 8)>>>(gal, prob);
    qaconv_gemm<<<G_ * P_, 256, SMEM_BYTES>>>(bnw, bnb, bnm, bnv, fcw, fcb,
                                              lbnw, lbnb, lbnm, lbnv, out);
}

// round 12
// speedup vs baseline: 2.7797x; 1.3210x over previous
#include <cuda_runtime.h>
#include <cuda_bf16.h>
#include <cstdint>
#include <math.h>

// ============================================================================
// QAConv bf16 persistent: s[g,p,i,j] = <ker[p,i,:], gal[g,:,j]> (channel-L2-
// normalized), score = sigmoid(lbn(fc(bn([colmax|rowmax])))/10).
//
// Legacy-path HMMA.16816 (bf16/f32) is the fastest mma.sync on this build
// (8-bit variants measured de-rated; tcgen05 unavailable: ptxas target
// sm_103). Persistent CTAs (1/SM), continuous 3-stage cp.async ring across
// pair boundaries so next pair's loads overlap this pair's epilogue.
// ============================================================================

#define G_ 64
#define P_ 64
#define D_ 512
#define HW_ 192
#define NPAIR (G_ * P_)

__device__ __nv_bfloat16 g_kerA[(size_t)P_ * HW_ * D_];   // [p][i][k] K-major
__device__ __nv_bfloat16 g_galB[(size_t)G_ * HW_ * D_];   // [g][j][k] K-major
__device__ float g_scale[128 * HW_];                      // [z][j] 1/norm

// ------------------------- Kernel 1: column norms --------------------------
__global__ void __launch_bounds__(768) norm_kernel(const float* __restrict__ gal,
                                                   const float* __restrict__ prob) {
    __shared__ float ssum[4][HW_];
    int b = blockIdx.x;                 // 0..127
    int j = threadIdx.x;                // 0..191
    int ty = threadIdx.y;               // 0..3
    const float* src = (b < 64) ? (gal + (size_t)b * D_ * HW_)
                                : (prob + (size_t)(b - 64) * D_ * HW_);
    float ss = 0.f;
#pragma unroll 8
    for (int dd = 0; dd < 128; dd++) {
        float v = src[(size_t)(ty * 128 + dd) * HW_ + j];
        ss += v * v;
    }
    ssum[ty][j] = ss;
    __syncthreads();
    if (ty == 0) {
        ss = ssum[0][j] + ssum[1][j] + ssum[2][j] + ssum[3][j];
        g_scale[b * HW_ + j] = 1.f / fmaxf(sqrtf(ss), 1e-12f);
    }
}

// ------------------ Kernel 2: transpose + scale + bf16 ---------------------
__global__ void prep_kernel(const float* __restrict__ gal,
                            const float* __restrict__ prob) {
    __shared__ float tile[32][33];
    __shared__ float fj[32];
    int z = blockIdx.z;                 // 0..127
    int d0 = blockIdx.x * 32;           // 16 tiles
    int j0 = blockIdx.y * 32;           // 6 tiles
    int tx = threadIdx.x, ty = threadIdx.y;  // 32 x 8
    const float* src;
    __nv_bfloat16* dst;
    if (z < 64) {
        src = gal + (size_t)z * D_ * HW_;
        dst = g_galB + (size_t)z * HW_ * D_;
    } else {
        src = prob + (size_t)(z - 64) * D_ * HW_;
        dst = g_kerA + (size_t)(z - 64) * HW_ * D_;
    }
#pragma unroll
    for (int r = 0; r < 32; r += 8)
        tile[ty + r][tx] = src[(size_t)(d0 + ty + r) * HW_ + j0 + tx];
    if (ty == 0) fj[tx] = g_scale[z * HW_ + j0 + tx];
    __syncthreads();

    int tid = ty * 32 + tx;
    int jl = tid >> 3;                  // 0..31 (j within tile)
    int d4 = (tid & 7) * 4;             // 0,4,..,28 (d within tile)
    float f = fj[jl];
    __nv_bfloat162 lo = __floats2bfloat162_rn(tile[d4 + 0][jl] * f,
                                              tile[d4 + 1][jl] * f);
    __nv_bfloat162 hi = __floats2bfloat162_rn(tile[d4 + 2][jl] * f,
                                              tile[d4 + 3][jl] * f);
    uint2 packed = make_uint2(*(uint32_t*)&lo, *(uint32_t*)&hi);
    *(uint2*)(dst + (size_t)(j0 + jl) * D_ + d0 + d4) = packed;
}

// ------------------------------ helpers ------------------------------
__device__ __forceinline__ uint32_t smem_u32(const void* p) {
    return (uint32_t)__cvta_generic_to_shared(p);
}
__device__ __forceinline__ void cpasync16(uint32_t dst, const void* src) {
    asm volatile("cp.async.cg.shared.global [%0], [%1], 16;"
                 :: "r"(dst), "l"(src) : "memory");
}
__device__ __forceinline__ void ldsm4(uint32_t& r0, uint32_t& r1,
                                      uint32_t& r2, uint32_t& r3,
                                      uint32_t addr) {
    asm volatile("ldmatrix.sync.aligned.m8n8.x4.shared.b16 {%0,%1,%2,%3}, [%4];"
                 : "=r"(r0), "=r"(r1), "=r"(r2), "=r"(r3) : "r"(addr));
}
__device__ __forceinline__ void mma16816(float* c, const uint32_t* a,
                                         uint32_t b0, uint32_t b1) {
    asm volatile(
        "mma.sync.aligned.m16n8k16.row.col.f32.bf16.bf16.f32 "
        "{%0,%1,%2,%3}, {%4,%5,%6,%7}, {%8,%9}, {%0,%1,%2,%3};"
        : "+f"(c[0]), "+f"(c[1]), "+f"(c[2]), "+f"(c[3])
        : "r"(a[0]), "r"(a[1]), "r"(a[2]), "r"(a[3]), "r"(b0), "r"(b1));
}

#define SWZ(x) ((x) ^ (((x) >> 3) & 0x70))

// SMEM: 3-stage ring; stage = A 192x128B (24KB) + B 192x128B (24KB) = 48KB
#define OFF_BUF    1024
#define CH_BYTES   49152
#define STG(s)     (OFF_BUF + (s) * CH_BYTES)
#define OFF_ROWP   (OFF_BUF + 3 * CH_BYTES)            // rowp[2][192] f32
#define OFF_COLP   (OFF_ROWP + 2 * 192 * 4)            // colp[4][192] f32
#define OFF_RED    (OFF_COLP + 4 * 192 * 4)            // red[8]
#define SMEM_BYTES (OFF_RED + 64)

// Issue all cp.async for chunk c (K in [c*64,(c+1)*64)) of `pair` into stage st
__device__ __forceinline__ void load_chunk(uint32_t sbase, int pair, int c,
                                           int st, int tid) {
    const __nv_bfloat16* Ag = g_kerA + (size_t)(pair & 63) * HW_ * D_;
    const __nv_bfloat16* Bg = g_galB + (size_t)(pair >> 6) * HW_ * D_;
    const uint32_t sb_ = sbase + STG(st);
#pragma unroll
    for (int i = 0; i < 12; i++) {
        int gid2 = tid + i * 256;
        bool isA = gid2 < 1536;
        int lg = isA ? gid2 : gid2 - 1536;
        int row = lg >> 3, seg = lg & 7;
        const __nv_bfloat16* src =
            (isA ? Ag : Bg) + (size_t)row * D_ + c * 64 + seg * 8;
        uint32_t dst = sb_ + (isA ? 0 : 24576) + SWZ(row * 128 + seg * 16);
        cpasync16(dst, src);
    }
    asm volatile("cp.async.commit_group;" ::: "memory");
}

// ----------------- Kernel 3: persistent GEMM + fused epilogue -------------
__global__ void __launch_bounds__(256, 1) qaconv_gemm(
    const float* __restrict__ bnw, const float* __restrict__ bnb,
    const float* __restrict__ bnm, const float* __restrict__ bnv,
    const float* __restrict__ fcw, const float* __restrict__ fcb,
    const float* __restrict__ lbnw, const float* __restrict__ lbnb,
    const float* __restrict__ lbnm, const float* __restrict__ lbnv,
    float* __restrict__ out)
{
    extern __shared__ char smem[];
    const uint32_t sbase = smem_u32(smem);
    const int tid = threadIdx.x;
    const int wid = tid >> 5;
    const int lane = tid & 31;
    const int warp_m = wid & 3;        // 4 strips of 48 rows (probe i)
    const int warp_n = wid >> 2;       // 2 strips of 96 cols (gallery j)
    const int bid = blockIdx.x;
    const int gstride = gridDim.x;

    const int T = (NPAIR - bid + gstride - 1) / gstride;   // pairs for this CTA
    if (T <= 0) return;
    const int lastLc = T * 8 - 1;

    const float a_bn = bnw[0] * rsqrtf(bnv[0] + 1e-5f);
    const float b_bn = bnb[0] - bnm[0] * a_bn;
    const float a_lbn = lbnw[0] * rsqrtf(lbnv[0] + 1e-5f);
    const float b0_lbn = lbnb[0] - lbnm[0] * a_lbn;
    const float fcb0 = fcb[0];

    float* rowp = (float*)(smem + OFF_ROWP);   // [2][192]
    float* colp = (float*)(smem + OFF_COLP);   // [4][192]
    float* red  = (float*)(smem + OFF_RED);

    // prologue: first two chunks of first pair
    load_chunk(sbase, bid, 0, 0, tid);
    load_chunk(sbase, bid, 1, 1, tid);

#pragma unroll 1
    for (int t = 0; t < T; t++) {
        const int pair = bid + t * gstride;

        float acc[3][12][4];
#pragma unroll
        for (int mt = 0; mt < 3; mt++)
#pragma unroll
            for (int nt = 0; nt < 12; nt++)
#pragma unroll
                for (int q = 0; q < 4; q++) acc[mt][nt][q] = 0.f;

#pragma unroll 1
        for (int c = 0; c < 8; c++) {
            const int lc = t * 8 + c;
            if (lc == lastLc)
                asm volatile("cp.async.wait_group 0;" ::: "memory");
            else
                asm volatile("cp.async.wait_group 1;" ::: "memory");
            __syncthreads();

            const uint32_t ab = sbase + STG(lc % 3);
            const uint32_t bb = ab + 24576;
            const int arowb = (warp_m * 48 + (lane & 15)) * 128;
            const int brow  = warp_n * 96 + (lane & 7) + ((lane >> 4) << 3);
#pragma unroll
            for (int ks = 0; ks < 4; ks++) {
                const int akb = ks * 32 + ((lane >> 4) << 4);
                const int bkb = ks * 32 + (((lane >> 3) & 1) << 4);
                uint32_t a[3][4];
#pragma unroll
                for (int mt = 0; mt < 3; mt++)
                    ldsm4(a[mt][0], a[mt][1], a[mt][2], a[mt][3],
                          ab + SWZ(arowb + mt * 2048 + akb));
                uint32_t bf[6][4];
#pragma unroll
                for (int nt2 = 0; nt2 < 6; nt2++)
                    ldsm4(bf[nt2][0], bf[nt2][1], bf[nt2][2], bf[nt2][3],
                          bb + SWZ((brow + nt2 * 16) * 128 + bkb));
#pragma unroll
                for (int mt = 0; mt < 3; mt++)
#pragma unroll
                    for (int nt2 = 0; nt2 < 6; nt2++) {
                        mma16816(acc[mt][nt2 * 2 + 0], a[mt], bf[nt2][0], bf[nt2][1]);
                        mma16816(acc[mt][nt2 * 2 + 1], a[mt], bf[nt2][2], bf[nt2][3]);
                    }
            }
            // prefetch chunk lc+2 (may belong to the next pair)
            const int lcn = lc + 2;
            if (lcn <= lastLc) {
                const int pairN = bid + (lcn >> 3) * gstride;
                load_chunk(sbase, pairN, lcn & 7, lcn % 3, tid);
            }
        }

        // -------- epilogue: dual max + BN/fc/LBN/sigmoid (overlaps next loads)
        // acc[mt][nt][q]: row = warp_m*48 + mt*16 + lane/4 + (q>=2)*8
        //                 col = warp_n*96 + nt*8 + (lane%4)*2 + (q&1)
        float rm[6];
#pragma unroll
        for (int mt = 0; mt < 3; mt++) {
            float r0 = -3.4e38f, r1 = -3.4e38f;
#pragma unroll
            for (int nt = 0; nt < 12; nt++) {
                r0 = fmaxf(r0, fmaxf(acc[mt][nt][0], acc[mt][nt][1]));
                r1 = fmaxf(r1, fmaxf(acc[mt][nt][2], acc[mt][nt][3]));
            }
            rm[2 * mt] = r0; rm[2 * mt + 1] = r1;
        }
#pragma unroll
        for (int i = 0; i < 6; i++) {
            rm[i] = fmaxf(rm[i], __shfl_xor_sync(0xffffffffu, rm[i], 1));
            rm[i] = fmaxf(rm[i], __shfl_xor_sync(0xffffffffu, rm[i], 2));
        }
        if ((lane & 3) == 0) {
            int rbase = warp_m * 48 + (lane >> 2);
#pragma unroll
            for (int mt = 0; mt < 3; mt++) {
                rowp[warp_n * 192 + rbase + mt * 16]     = rm[2 * mt];
                rowp[warp_n * 192 + rbase + mt * 16 + 8] = rm[2 * mt + 1];
            }
        }

        float cm[24];
#pragma unroll
        for (int nt = 0; nt < 12; nt++) {
            float c0 = -3.4e38f, c1 = -3.4e38f;
#pragma unroll
            for (int mt = 0; mt < 3; mt++) {
                c0 = fmaxf(c0, fmaxf(acc[mt][nt][0], acc[mt][nt][2]));
                c1 = fmaxf(c1, fmaxf(acc[mt][nt][1], acc[mt][nt][3]));
            }
            cm[2 * nt] = c0; cm[2 * nt + 1] = c1;
        }
#pragma unroll
        for (int i = 0; i < 24; i++) {
            cm[i] = fmaxf(cm[i], __shfl_xor_sync(0xffffffffu, cm[i], 4));
            cm[i] = fmaxf(cm[i], __shfl_xor_sync(0xffffffffu, cm[i], 8));
            cm[i] = fmaxf(cm[i], __shfl_xor_sync(0xffffffffu, cm[i], 16));
        }
        if (lane < 4) {
            int cbase = warp_n * 96 + lane * 2;
#pragma unroll
            for (int nt = 0; nt < 12; nt++) {
                colp[warp_m * 192 + cbase + nt * 8]     = cm[2 * nt];
                colp[warp_m * 192 + cbase + nt * 8 + 1] = cm[2 * nt + 1];
            }
        }
        __syncthreads();

        float part = 0.f;
        if (tid < 192) {
            float cmax = fmaxf(fmaxf(colp[tid], colp[192 + tid]),
                               fmaxf(colp[384 + tid], colp[576 + tid]));
            float rmax = fmaxf(rowp[tid], rowp[192 + tid]);
            part = fcw[tid]       * (a_bn * cmax + b_bn)   // s.max(axis=2), idx j
                 + fcw[192 + tid] * (a_bn * rmax + b_bn);  // s.max(axis=3), idx i
        }
#pragma unroll
        for (int o = 16; o > 0; o >>= 1)
            part += __shfl_down_sync(0xffffffffu, part, o);
        if (lane == 0) red[wid] = part;
        __syncthreads();
        if (tid == 0) {
            float s = red[0] + red[1] + red[2] + red[3] +
                      red[4] + red[5] + red[6] + red[7];
            s += fcb0;
            float y = s * a_lbn + b0_lbn;
            out[pair] = 1.f / (1.f + expf(-y * 0.1f));
        }
    }
}

// ------------------------------ launch ---------------------------------------
extern "C" void kernel_launch(void* const* d_in, const int* in_sizes, int n_in,
                              void* d_out, int out_size) {
    const float* gal  = (const float*)d_in[0];
    const float* prob = (const float*)d_in[1];
    const float* bnw  = (const float*)d_in[2];
    const float* bnb  = (const float*)d_in[3];
    const float* bnm  = (const float*)d_in[4];
    const float* bnv  = (const float*)d_in[5];
    const float* fcw  = (const float*)d_in[6];
    const float* fcb  = (const float*)d_in[7];
    const float* lbnw = (const float*)d_in[8];
    const float* lbnb = (const float*)d_in[9];
    const float* lbnm = (const float*)d_in[10];
    const float* lbnv = (const float*)d_in[11];
    float* out = (float*)d_out;

    int sms = 0;
    cudaDeviceGetAttribute(&sms, cudaDevAttrMultiProcessorCount, 0);
    if (sms <= 0) sms = 148;
    if (sms > NPAIR) sms = NPAIR;

    cudaFuncSetAttribute(qaconv_gemm, cudaFuncAttributeMaxDynamicSharedMemorySize,
                         SMEM_BYTES);

    norm_kernel<<<128, dim3(192, 4)>>>(gal, prob);
    prep_kernel<<<dim3(16, 6, 128), dim3(32, 8)>>>(gal, prob);
    qaconv_gemm<<<sms, 256, SMEM_BYTES>>>(bnw, bnb, bnm, bnv, fcw, fcb,
                                          lbnw, lbnb, lbnm, lbnv, out);
}

// round 13
// speedup vs baseline: 2.8343x; 1.0196x over previous
#include <cuda_runtime.h>
#include <cuda_fp16.h>
#include <cstdint>
#include <math.h>

// ============================================================================
// QAConv fp16 persistent: s[g,p,i,j] = <ker[p,i,:], gal[g,:,j]> (channel-L2-
// normalized), score = sigmoid(lbn(fc(bn([colmax|rowmax])))/10).
//
// Experiment vs R12 (bf16/f32acc, 389us): fp16 operands + fp16 accumulators
// via mma.sync.m16n8k16.f16.f16.f16.f16 — on archs with a legacy-path rate
// split, f16-acc is the full-rate variant. Normalized inputs (|x|<=1) make
// f16 operands MORE accurate than bf16; f16 accumulation over K=512 adds
// ~8e-3 abs error on s -> predicted final rel_err ~1.5e-4.
// Pipeline identical: persistent CTAs, 3-stage cp.async ring across pair
// boundaries, fused dual-max epilogue.
// ============================================================================

#define G_ 64
#define P_ 64
#define D_ 512
#define HW_ 192
#define NPAIR (G_ * P_)

__device__ __half g_kerA[(size_t)P_ * HW_ * D_];   // [p][i][k] K-major
__device__ __half g_galB[(size_t)G_ * HW_ * D_];   // [g][j][k] K-major
__device__ float g_scale[128 * HW_];               // [z][j] 1/norm

// ------------------------- Kernel 1: column norms --------------------------
__global__ void __launch_bounds__(768) norm_kernel(const float* __restrict__ gal,
                                                   const float* __restrict__ prob) {
    __shared__ float ssum[4][HW_];
    int b = blockIdx.x;                 // 0..127
    int j = threadIdx.x;                // 0..191
    int ty = threadIdx.y;               // 0..3
    const float* src = (b < 64) ? (gal + (size_t)b * D_ * HW_)
                                : (prob + (size_t)(b - 64) * D_ * HW_);
    float ss = 0.f;
#pragma unroll 8
    for (int dd = 0; dd < 128; dd++) {
        float v = src[(size_t)(ty * 128 + dd) * HW_ + j];
        ss += v * v;
    }
    ssum[ty][j] = ss;
    __syncthreads();
    if (ty == 0) {
        ss = ssum[0][j] + ssum[1][j] + ssum[2][j] + ssum[3][j];
        g_scale[b * HW_ + j] = 1.f / fmaxf(sqrtf(ss), 1e-12f);
    }
}

// ------------------ Kernel 2: transpose + scale + f16 ----------------------
__global__ void prep_kernel(const float* __restrict__ gal,
                            const float* __restrict__ prob) {
    __shared__ float tile[32][33];
    __shared__ float fj[32];
    int z = blockIdx.z;                 // 0..127
    int d0 = blockIdx.x * 32;           // 16 tiles
    int j0 = blockIdx.y * 32;           // 6 tiles
    int tx = threadIdx.x, ty = threadIdx.y;  // 32 x 8
    const float* src;
    __half* dst;
    if (z < 64) {
        src = gal + (size_t)z * D_ * HW_;
        dst = g_galB + (size_t)z * HW_ * D_;
    } else {
        src = prob + (size_t)(z - 64) * D_ * HW_;
        dst = g_kerA + (size_t)(z - 64) * HW_ * D_;
    }
#pragma unroll
    for (int r = 0; r < 32; r += 8)
        tile[ty + r][tx] = src[(size_t)(d0 + ty + r) * HW_ + j0 + tx];
    if (ty == 0) fj[tx] = g_scale[z * HW_ + j0 + tx];
    __syncthreads();

    int tid = ty * 32 + tx;
    int jl = tid >> 3;                  // 0..31 (j within tile)
    int d4 = (tid & 7) * 4;             // 0,4,..,28 (d within tile)
    float f = fj[jl];
    __half2 lo = __floats2half2_rn(tile[d4 + 0][jl] * f, tile[d4 + 1][jl] * f);
    __half2 hi = __floats2half2_rn(tile[d4 + 2][jl] * f, tile[d4 + 3][jl] * f);
    uint2 packed = make_uint2(*(uint32_t*)&lo, *(uint32_t*)&hi);
    *(uint2*)(dst + (size_t)(j0 + jl) * D_ + d0 + d4) = packed;
}

// ------------------------------ helpers ------------------------------
__device__ __forceinline__ uint32_t smem_u32(const void* p) {
    return (uint32_t)__cvta_generic_to_shared(p);
}
__device__ __forceinline__ void cpasync16(uint32_t dst, const void* src) {
    asm volatile("cp.async.cg.shared.global [%0], [%1], 16;"
                 :: "r"(dst), "l"(src) : "memory");
}
__device__ __forceinline__ void ldsm4(uint32_t& r0, uint32_t& r1,
                                      uint32_t& r2, uint32_t& r3,
                                      uint32_t addr) {
    asm volatile("ldmatrix.sync.aligned.m8n8.x4.shared.b16 {%0,%1,%2,%3}, [%4];"
                 : "=r"(r0), "=r"(r1), "=r"(r2), "=r"(r3) : "r"(addr));
}
// f16 x f16 -> f16 accumulate. D/C = 2x b32 (4 halves):
//   reg0 = {(row r, col c), (row r, col c+1)}
//   reg1 = {(row r+8, col c), (row r+8, col c+1)}
__device__ __forceinline__ void mma16816h(uint32_t* c, const uint32_t* a,
                                          uint32_t b0, uint32_t b1) {
    asm volatile(
        "mma.sync.aligned.m16n8k16.row.col.f16.f16.f16.f16 "
        "{%0,%1}, {%2,%3,%4,%5}, {%6,%7}, {%0,%1};"
        : "+r"(c[0]), "+r"(c[1])
        : "r"(a[0]), "r"(a[1]), "r"(a[2]), "r"(a[3]), "r"(b0), "r"(b1));
}

#define SWZ(x) ((x) ^ (((x) >> 3) & 0x70))

// SMEM: 3-stage ring; stage = A 192x128B (24KB) + B 192x128B (24KB) = 48KB
#define OFF_BUF    1024
#define CH_BYTES   49152
#define STG(s)     (OFF_BUF + (s) * CH_BYTES)
#define OFF_ROWP   (OFF_BUF + 3 * CH_BYTES)            // rowp[2][192] f32
#define OFF_COLP   (OFF_ROWP + 2 * 192 * 4)            // colp[4][192] f32
#define OFF_RED    (OFF_COLP + 4 * 192 * 4)            // red[8]
#define SMEM_BYTES (OFF_RED + 64)

// Issue all cp.async for chunk c (K in [c*64,(c+1)*64)) of `pair` into stage st
__device__ __forceinline__ void load_chunk(uint32_t sbase, int pair, int c,
                                           int st, int tid) {
    const __half* Ag = g_kerA + (size_t)(pair & 63) * HW_ * D_;
    const __half* Bg = g_galB + (size_t)(pair >> 6) * HW_ * D_;
    const uint32_t sb_ = sbase + STG(st);
#pragma unroll
    for (int i = 0; i < 12; i++) {
        int gid2 = tid + i * 256;
        bool isA = gid2 < 1536;
        int lg = isA ? gid2 : gid2 - 1536;
        int row = lg >> 3, seg = lg & 7;
        const __half* src =
            (isA ? Ag : Bg) + (size_t)row * D_ + c * 64 + seg * 8;
        uint32_t dst = sb_ + (isA ? 0 : 24576) + SWZ(row * 128 + seg * 16);
        cpasync16(dst, src);
    }
    asm volatile("cp.async.commit_group;" ::: "memory");
}

// ----------------- Kernel 3: persistent GEMM + fused epilogue -------------
__global__ void __launch_bounds__(256, 1) qaconv_gemm(
    const float* __restrict__ bnw, const float* __restrict__ bnb,
    const float* __restrict__ bnm, const float* __restrict__ bnv,
    const float* __restrict__ fcw, const float* __restrict__ fcb,
    const float* __restrict__ lbnw, const float* __restrict__ lbnb,
    const float* __restrict__ lbnm, const float* __restrict__ lbnv,
    float* __restrict__ out)
{
    extern __shared__ char smem[];
    const uint32_t sbase = smem_u32(smem);
    const int tid = threadIdx.x;
    const int wid = tid >> 5;
    const int lane = tid & 31;
    const int warp_m = wid & 3;        // 4 strips of 48 rows (probe i)
    const int warp_n = wid >> 2;       // 2 strips of 96 cols (gallery j)
    const int bid = blockIdx.x;
    const int gstride = gridDim.x;

    const int T = (NPAIR - bid + gstride - 1) / gstride;   // pairs for this CTA
    if (T <= 0) return;
    const int lastLc = T * 8 - 1;

    const float a_bn = bnw[0] * rsqrtf(bnv[0] + 1e-5f);
    const float b_bn = bnb[0] - bnm[0] * a_bn;
    const float a_lbn = lbnw[0] * rsqrtf(lbnv[0] + 1e-5f);
    const float b0_lbn = lbnb[0] - lbnm[0] * a_lbn;
    const float fcb0 = fcb[0];

    float* rowp = (float*)(smem + OFF_ROWP);   // [2][192]
    float* colp = (float*)(smem + OFF_COLP);   // [4][192]
    float* red  = (float*)(smem + OFF_RED);

    // prologue: first two chunks of first pair
    load_chunk(sbase, bid, 0, 0, tid);
    load_chunk(sbase, bid, 1, 1, tid);

#pragma unroll 1
    for (int t = 0; t < T; t++) {
        const int pair = bid + t * gstride;

        uint32_t acc[3][12][2];          // f16x2 accumulators
#pragma unroll
        for (int mt = 0; mt < 3; mt++)
#pragma unroll
            for (int nt = 0; nt < 12; nt++) {
                acc[mt][nt][0] = 0u;
                acc[mt][nt][1] = 0u;
            }

#pragma unroll 1
        for (int c = 0; c < 8; c++) {
            const int lc = t * 8 + c;
            if (lc == lastLc)
                asm volatile("cp.async.wait_group 0;" ::: "memory");
            else
                asm volatile("cp.async.wait_group 1;" ::: "memory");
            __syncthreads();

            const uint32_t ab = sbase + STG(lc % 3);
            const uint32_t bb = ab + 24576;
            const int arowb = (warp_m * 48 + (lane & 15)) * 128;
            const int brow  = warp_n * 96 + (lane & 7) + ((lane >> 4) << 3);
#pragma unroll
            for (int ks = 0; ks < 4; ks++) {
                const int akb = ks * 32 + ((lane >> 4) << 4);
                const int bkb = ks * 32 + (((lane >> 3) & 1) << 4);
                uint32_t a[3][4];
#pragma unroll
                for (int mt = 0; mt < 3; mt++)
                    ldsm4(a[mt][0], a[mt][1], a[mt][2], a[mt][3],
                          ab + SWZ(arowb + mt * 2048 + akb));
                uint32_t bf[6][4];
#pragma unroll
                for (int nt2 = 0; nt2 < 6; nt2++)
                    ldsm4(bf[nt2][0], bf[nt2][1], bf[nt2][2], bf[nt2][3],
                          bb + SWZ((brow + nt2 * 16) * 128 + bkb));
#pragma unroll
                for (int mt = 0; mt < 3; mt++)
#pragma unroll
                    for (int nt2 = 0; nt2 < 6; nt2++) {
                        mma16816h(acc[mt][nt2 * 2 + 0], a[mt], bf[nt2][0], bf[nt2][1]);
                        mma16816h(acc[mt][nt2 * 2 + 1], a[mt], bf[nt2][2], bf[nt2][3]);
                    }
            }
            // prefetch chunk lc+2 (may belong to the next pair)
            const int lcn = lc + 2;
            if (lcn <= lastLc) {
                const int pairN = bid + (lcn >> 3) * gstride;
                load_chunk(sbase, pairN, lcn & 7, lcn % 3, tid);
            }
        }

        // -------- epilogue: dual max + BN/fc/LBN/sigmoid (overlaps next loads)
        // acc[mt][nt][0] = {(r,c),(r,c+1)}, [1] = {(r+8,c),(r+8,c+1)}
        //   r = warp_m*48 + mt*16 + lane/4, c = warp_n*96 + nt*8 + (lane%4)*2
        const __half2 NEGINF = __float2half2_rn(-60000.f);

        float rm[6];
#pragma unroll
        for (int mt = 0; mt < 3; mt++) {
            __half2 m0 = NEGINF, m1 = NEGINF;
#pragma unroll
            for (int nt = 0; nt < 12; nt++) {
                m0 = __hmax2(m0, *(__half2*)&acc[mt][nt][0]);
                m1 = __hmax2(m1, *(__half2*)&acc[mt][nt][1]);
            }
            rm[2 * mt]     = fmaxf(__low2float(m0), __high2float(m0));
            rm[2 * mt + 1] = fmaxf(__low2float(m1), __high2float(m1));
        }
#pragma unroll
        for (int i = 0; i < 6; i++) {
            rm[i] = fmaxf(rm[i], __shfl_xor_sync(0xffffffffu, rm[i], 1));
            rm[i] = fmaxf(rm[i], __shfl_xor_sync(0xffffffffu, rm[i], 2));
        }
        if ((lane & 3) == 0) {
            int rbase = warp_m * 48 + (lane >> 2);
#pragma unroll
            for (int mt = 0; mt < 3; mt++) {
                rowp[warp_n * 192 + rbase + mt * 16]     = rm[2 * mt];
                rowp[warp_n * 192 + rbase + mt * 16 + 8] = rm[2 * mt + 1];
            }
        }

        float cm[24];
#pragma unroll
        for (int nt = 0; nt < 12; nt++) {
            __half2 mc = NEGINF;
#pragma unroll
            for (int mt = 0; mt < 3; mt++)
                mc = __hmax2(mc, __hmax2(*(__half2*)&acc[mt][nt][0],
                                         *(__half2*)&acc[mt][nt][1]));
            cm[2 * nt]     = __low2float(mc);
            cm[2 * nt + 1] = __high2float(mc);
        }
#pragma unroll
        for (int i = 0; i < 24; i++) {
            cm[i] = fmaxf(cm[i], __shfl_xor_sync(0xffffffffu, cm[i], 4));
            cm[i] = fmaxf(cm[i], __shfl_xor_sync(0xffffffffu, cm[i], 8));
            cm[i] = fmaxf(cm[i], __shfl_xor_sync(0xffffffffu, cm[i], 16));
        }
        if (lane < 4) {
            int cbase = warp_n * 96 + lane * 2;
#pragma unroll
            for (int nt = 0; nt < 12; nt++) {
                colp[warp_m * 192 + cbase + nt * 8]     = cm[2 * nt];
                colp[warp_m * 192 + cbase + nt * 8 + 1] = cm[2 * nt + 1];
            }
        }
        __syncthreads();

        float part = 0.f;
        if (tid < 192) {
            float cmax = fmaxf(fmaxf(colp[tid], colp[192 + tid]),
                               fmaxf(colp[384 + tid], colp[576 + tid]));
            float rmax = fmaxf(rowp[tid], rowp[192 + tid]);
            part = fcw[tid]       * (a_bn * cmax + b_bn)   // s.max(axis=2), idx j
                 + fcw[192 + tid] * (a_bn * rmax + b_bn);  // s.max(axis=3), idx i
        }
#pragma unroll
        for (int o = 16; o > 0; o >>= 1)
            part += __shfl_down_sync(0xffffffffu, part, o);
        if (lane == 0) red[wid] = part;
        __syncthreads();
        if (tid == 0) {
            float s = red[0] + red[1] + red[2] + red[3] +
                      red[4] + red[5] + red[6] + red[7];
            s += fcb0;
            float y = s * a_lbn + b0_lbn;
            out[pair] = 1.f / (1.f + expf(-y * 0.1f));
        }
    }
}

// ------------------------------ launch ---------------------------------------
extern "C" void kernel_launch(void* const* d_in, const int* in_sizes, int n_in,
                              void* d_out, int out_size) {
    const float* gal  = (const float*)d_in[0];
    const float* prob = (const float*)d_in[1];
    const float* bnw  = (const float*)d_in[2];
    const float* bnb  = (const float*)d_in[3];
    const float* bnm  = (const float*)d_in[4];
    const float* bnv  = (const float*)d_in[5];
    const float* fcw  = (const float*)d_in[6];
    const float* fcb  = (const float*)d_in[7];
    const float* lbnw = (const float*)d_in[8];
    const float* lbnb = (const float*)d_in[9];
    const float* lbnm = (const float*)d_in[10];
    const float* lbnv = (const float*)d_in[11];
    float* out = (float*)d_out;

    int sms = 0;
    cudaDeviceGetAttribute(&sms, cudaDevAttrMultiProcessorCount, 0);
    if (sms <= 0) sms = 148;
    if (sms > NPAIR) sms = NPAIR;

    cudaFuncSetAttribute(qaconv_gemm, cudaFuncAttributeMaxDynamicSharedMemorySize,
                         SMEM_BYTES);

    norm_kernel<<<128, dim3(192, 4)>>>(gal, prob);
    prep_kernel<<<dim3(16, 6, 128), dim3(32, 8)>>>(gal, prob);
    qaconv_gemm<<<sms, 256, SMEM_BYTES>>>(bnw, bnb, bnm, bnv, fcw, fcb,
                                          lbnw, lbnb, lbnm, lbnv, out);
}